// round 1
// baseline (speedup 1.0000x reference)
#include <cuda_runtime.h>
#include <cuda_bf16.h>
#include <math.h>

// FBPINN: 16 subdomains, MLP 1 -> 128 -> 128 -> 128 -> 128 -> 1 (tanh), windowed sum.
// N_PTS = 65536. One block handles 128 points for ALL 16 subdomains (no atomics).
// smem: W tile 64KB + hA 64KB + hB 64KB + x 512B  (dynamic, ~197KB, 1 CTA/SM).

#define NPTS_TOTAL 65536
#define NP   128      // points per block
#define NSUB 16
#define WID  128
#define NHID 3        // DEPTH-1 hidden layers

#define SMEM_FLOATS (WID*WID + WID*NP + WID*NP + NP)

__global__ void __launch_bounds__(256, 1) fbpinn_fp32_kernel(
    const float* __restrict__ x,
    const float* __restrict__ W0,      // [16,128,1]
    const float* __restrict__ b0,      // [16,128]
    const float* __restrict__ Wh,      // [16,3,128,128]
    const float* __restrict__ bh,      // [16,3,128]
    const float* __restrict__ Wout,    // [16,1,128]
    const float* __restrict__ bout,    // [16,1]
    const float* __restrict__ centres, // [16,1]
    const float* __restrict__ scales,  // [16,1]
    const float* __restrict__ mu_min,  // [16,1]
    const float* __restrict__ sd_min,  // [16,1]
    const float* __restrict__ mu_max,  // [16,1]
    const float* __restrict__ sd_max,  // [16,1]
    float* __restrict__ out)           // [65536,1]
{
    extern __shared__ float smem[];
    float* Wsm = smem;                    // [128][128]
    float* hA  = smem + WID*WID;          // [128][128]  (neuron-major: h[v][p])
    float* hB  = hA + WID*NP;             // [128][128]
    float* xs  = hB + WID*NP;             // [128]

    const int tid  = threadIdx.x;
    const int pblk = blockIdx.x * NP;

    if (tid < NP) xs[tid] = x[pblk + tid];
    __syncthreads();

    const int pcol = tid & 15;   // 0..15
    const int nrow = tid >> 4;   // 0..15
    const int p0   = pcol * 8;
    const int v0   = nrow * 8;

    float result = 0.0f;         // valid for tid < NP

    for (int s = 0; s < NSUB; s++) {
        const float centre = centres[s];
        const float scale  = fmaxf(scales[s], 1e-8f);
        const float inv_scale = 1.0f / scale;

        // ---------- layer 0: hA[v][p] = tanh(W0[s][v] * xi[p] + b0[s][v]) ----------
        #pragma unroll
        for (int dn = 0; dn < 8; dn++) {
            const int v = v0 + dn;
            const float w0v = W0[s*WID + v];
            const float b0v = b0[s*WID + v];
            float4 t0, t1;
            float xi;
            xi = (xs[p0+0] - centre) * inv_scale; t0.x = tanhf(fmaf(w0v, xi, b0v));
            xi = (xs[p0+1] - centre) * inv_scale; t0.y = tanhf(fmaf(w0v, xi, b0v));
            xi = (xs[p0+2] - centre) * inv_scale; t0.z = tanhf(fmaf(w0v, xi, b0v));
            xi = (xs[p0+3] - centre) * inv_scale; t0.w = tanhf(fmaf(w0v, xi, b0v));
            xi = (xs[p0+4] - centre) * inv_scale; t1.x = tanhf(fmaf(w0v, xi, b0v));
            xi = (xs[p0+5] - centre) * inv_scale; t1.y = tanhf(fmaf(w0v, xi, b0v));
            xi = (xs[p0+6] - centre) * inv_scale; t1.z = tanhf(fmaf(w0v, xi, b0v));
            xi = (xs[p0+7] - centre) * inv_scale; t1.w = tanhf(fmaf(w0v, xi, b0v));
            *(float4*)&hA[v*NP + p0]     = t0;
            *(float4*)&hA[v*NP + p0 + 4] = t1;
        }
        __syncthreads();

        // ---------- hidden layers ----------
        float* hin  = hA;
        float* hout = hB;
        for (int l = 0; l < NHID; l++) {
            // stage weights: Wh[s][l][v][w] -> Wsm[v][w]
            {
                const float4* gw = (const float4*)(Wh + ((size_t)(s*NHID + l)) * WID * WID);
                float4* sw = (float4*)Wsm;
                #pragma unroll
                for (int i = tid; i < WID*WID/4; i += 256) sw[i] = gw[i];
            }
            __syncthreads();

            float acc[8][8];
            {
                const float* bptr = bh + (s*NHID + l) * WID;
                #pragma unroll
                for (int dn = 0; dn < 8; dn++) {
                    const float b = bptr[v0 + dn];
                    #pragma unroll
                    for (int dp = 0; dp < 8; dp++) acc[dn][dp] = b;
                }
            }

            for (int wc = 0; wc < WID; wc += 4) {
                float hr[4][8];
                #pragma unroll
                for (int dw = 0; dw < 4; dw++) {
                    const float4 a = *(const float4*)&hin[(wc+dw)*NP + p0];
                    const float4 b = *(const float4*)&hin[(wc+dw)*NP + p0 + 4];
                    hr[dw][0]=a.x; hr[dw][1]=a.y; hr[dw][2]=a.z; hr[dw][3]=a.w;
                    hr[dw][4]=b.x; hr[dw][5]=b.y; hr[dw][6]=b.z; hr[dw][7]=b.w;
                }
                #pragma unroll
                for (int dn = 0; dn < 8; dn++) {
                    const float4 wv = *(const float4*)&Wsm[(v0+dn)*WID + wc];
                    #pragma unroll
                    for (int dp = 0; dp < 8; dp++) {
                        float a = acc[dn][dp];
                        a = fmaf(wv.x, hr[0][dp], a);
                        a = fmaf(wv.y, hr[1][dp], a);
                        a = fmaf(wv.z, hr[2][dp], a);
                        a = fmaf(wv.w, hr[3][dp], a);
                        acc[dn][dp] = a;
                    }
                }
            }

            // tanh + store to hout
            #pragma unroll
            for (int dn = 0; dn < 8; dn++) {
                const int v = v0 + dn;
                float4 t0, t1;
                t0.x = tanhf(acc[dn][0]); t0.y = tanhf(acc[dn][1]);
                t0.z = tanhf(acc[dn][2]); t0.w = tanhf(acc[dn][3]);
                t1.x = tanhf(acc[dn][4]); t1.y = tanhf(acc[dn][5]);
                t1.z = tanhf(acc[dn][6]); t1.w = tanhf(acc[dn][7]);
                *(float4*)&hout[v*NP + p0]     = t0;
                *(float4*)&hout[v*NP + p0 + 4] = t1;
            }
            __syncthreads();

            float* tmp = hin; hin = hout; hout = tmp;
        }

        // ---------- output layer + window (one thread per point) ----------
        if (tid < NP) {
            const int p = tid;
            float raw = bout[s];
            const float* wo = Wout + s*WID;
            #pragma unroll 8
            for (int v = 0; v < WID; v++) raw = fmaf(wo[v], hin[v*NP + p], raw);

            const float x0v = xs[p];
            const float zlo = (x0v - mu_min[s]) / sd_min[s];
            const float zhi = (mu_max[s] - x0v) / sd_max[s];
            const float wlo = 1.0f / (1.0f + expf(-zlo));
            const float whi = 1.0f / (1.0f + expf(-zhi));
            result = fmaf(wlo * whi, raw, result);
        }
        __syncthreads();
    }

    if (tid < NP) out[pblk + tid] = result;
}

extern "C" void kernel_launch(void* const* d_in, const int* in_sizes, int n_in,
                              void* d_out, int out_size) {
    const float* x       = (const float*)d_in[0];
    const float* W0      = (const float*)d_in[1];
    const float* b0      = (const float*)d_in[2];
    const float* Wh      = (const float*)d_in[3];
    const float* bh      = (const float*)d_in[4];
    const float* Wout    = (const float*)d_in[5];
    const float* bout    = (const float*)d_in[6];
    const float* centres = (const float*)d_in[7];
    const float* scales  = (const float*)d_in[8];
    const float* mu_min  = (const float*)d_in[9];
    const float* sd_min  = (const float*)d_in[10];
    const float* mu_max  = (const float*)d_in[11];
    const float* sd_max  = (const float*)d_in[12];
    float* out = (float*)d_out;

    const int smem_bytes = SMEM_FLOATS * (int)sizeof(float);
    static bool attr_set = false;
    if (!attr_set) {
        cudaFuncSetAttribute(fbpinn_fp32_kernel,
                             cudaFuncAttributeMaxDynamicSharedMemorySize, smem_bytes);
        attr_set = true;
    }

    const int nblocks = NPTS_TOTAL / NP;   // 512
    fbpinn_fp32_kernel<<<nblocks, 256, smem_bytes>>>(
        x, W0, b0, Wh, bh, Wout, bout, centres, scales,
        mu_min, sd_min, mu_max, sd_max, out);
}

// round 2
// speedup vs baseline: 1.2703x; 1.2703x over previous
#include <cuda_runtime.h>
#include <stdint.h>
#include <math.h>

// FBPINN: 16 subdomains, MLP 1->128->128->128->128->1 (tanh), windowed sum, N=65536.
// R2: packed fma.rn.f32x2 (neuron-pair packing), fast tanh via MUFU.EX2/RCP,
//     pre-transposed weights, 512 threads/CTA, register prefetch of weight tiles.

#define NPTS  65536
#define NP    128     // points per block
#define NSUB  16
#define WID   128
#define NHID  3
#define THREADS 512

#define SMEM_FLOATS (WID*WID + WID*NP + WID*NP + NP)

// Pre-transposed hidden weights: [s][l][w][v]
__device__ float g_WhT[NSUB*NHID*WID*WID];

__global__ void transpose_wh_kernel(const float* __restrict__ Wh) {
    int idx = blockIdx.x * blockDim.x + threadIdx.x;   // < NSUB*NHID*WID*WID
    int v  = idx & 127;
    int w  = (idx >> 7) & 127;
    int sl = idx >> 14;
    g_WhT[idx] = Wh[((size_t)sl * WID + v) * WID + w];
}

__device__ __forceinline__ uint64_t pack2(float a, float b) {
    uint64_t r; asm("mov.b64 %0,{%1,%2};" : "=l"(r) : "f"(a), "f"(b)); return r;
}
__device__ __forceinline__ uint64_t dup2(float a) { return pack2(a, a); }
__device__ __forceinline__ uint64_t fma2(uint64_t a, uint64_t b, uint64_t c) {
    uint64_t d; asm("fma.rn.f32x2 %0,%1,%2,%3;" : "=l"(d) : "l"(a), "l"(b), "l"(c)); return d;
}
__device__ __forceinline__ void unpack2(uint64_t v, float& a, float& b) {
    asm("mov.b64 {%0,%1},%2;" : "=f"(a), "=f"(b) : "l"(v));
}
__device__ __forceinline__ float fast_tanh(float x) {
    // tanh(x) = 1 - 2/(exp(2x)+1); __expf -> MUFU.EX2, __fdividef -> MUFU.RCP.
    float e = __expf(2.0f * x);
    return 1.0f - __fdividef(2.0f, e + 1.0f);
}
__device__ __forceinline__ float fast_sigmoid(float z) {
    return __fdividef(1.0f, 1.0f + __expf(-z));
}

__global__ void __launch_bounds__(THREADS, 1) fbpinn_f32x2_kernel(
    const float* __restrict__ x,
    const float* __restrict__ W0,      // [16,128]
    const float* __restrict__ b0,      // [16,128]
    const float* __restrict__ bh,      // [16,3,128]
    const float* __restrict__ Wout,    // [16,128]
    const float* __restrict__ bout,    // [16]
    const float* __restrict__ centres,
    const float* __restrict__ scales,
    const float* __restrict__ mu_min,
    const float* __restrict__ sd_min,
    const float* __restrict__ mu_max,
    const float* __restrict__ sd_max,
    float* __restrict__ out)
{
    extern __shared__ float smem[];
    float* Wsm = smem;                    // [w][v] 128x128 (transposed layout)
    float* hA  = smem + WID*WID;          // [v][p]
    float* hB  = hA + WID*NP;
    float* xs  = hB + WID*NP;             // [128]

    const int tid  = threadIdx.x;
    const int pblk = blockIdx.x * NP;

    if (tid < NP) xs[tid] = x[pblk + tid];
    __syncthreads();

    // Tile: 8 neurons (4 pairs) x 4 points per thread.
    const int p0 = (tid & 31) * 4;        // warp covers all 128 points
    const int v0 = (tid >> 5) * 8;        // warp has one neuron row -> weight LDS broadcast

    float result = 0.0f;                  // valid for tid < NP

    // Prefetch first weight tile (s=0, l=0) into registers.
    float4 wpre[8];
    {
        const float4* gw = (const float4*)g_WhT;
        #pragma unroll
        for (int k = 0; k < 8; k++) wpre[k] = gw[tid + k*THREADS];
    }

    for (int s = 0; s < NSUB; s++) {
        const float centre = centres[s];
        const float inv_scale = 1.0f / fmaxf(scales[s], 1e-8f);

        // ---------- layer 0 ----------
        {
            float xi0 = (xs[p0+0] - centre) * inv_scale;
            float xi1 = (xs[p0+1] - centre) * inv_scale;
            float xi2 = (xs[p0+2] - centre) * inv_scale;
            float xi3 = (xs[p0+3] - centre) * inv_scale;
            #pragma unroll
            for (int d = 0; d < 8; d++) {
                const int v = v0 + d;
                const float wv = W0[s*WID + v];
                const float bv = b0[s*WID + v];
                float4 t;
                t.x = fast_tanh(fmaf(wv, xi0, bv));
                t.y = fast_tanh(fmaf(wv, xi1, bv));
                t.z = fast_tanh(fmaf(wv, xi2, bv));
                t.w = fast_tanh(fmaf(wv, xi3, bv));
                *(float4*)&hA[v*NP + p0] = t;
            }
        }
        __syncthreads();

        float* hin  = hA;
        float* hout = hB;

        for (int l = 0; l < NHID; l++) {
            // Stage prefetched weight tile (s,l) into smem.
            {
                float4* sw = (float4*)Wsm;
                #pragma unroll
                for (int k = 0; k < 8; k++) sw[tid + k*THREADS] = wpre[k];
            }
            __syncthreads();

            // Prefetch next tile: (s,l+1) or (s+1,0); wrap harmlessly at the end.
            {
                int nsl = s*NHID + l + 1;
                if (nsl >= NSUB*NHID) nsl = 0;
                const float4* gw = (const float4*)(g_WhT + (size_t)nsl * WID * WID);
                #pragma unroll
                for (int k = 0; k < 8; k++) wpre[k] = gw[tid + k*THREADS];
            }

            // GEMM: acc[pair d][point p] over 4 neuron-pairs x 4 points.
            uint64_t acc[4][4];
            {
                const float* bptr = bh + (s*NHID + l)*WID + v0;
                float4 ba = *(const float4*)&bptr[0];
                float4 bb = *(const float4*)&bptr[4];
                uint64_t bp0 = pack2(ba.x, ba.y);
                uint64_t bp1 = pack2(ba.z, ba.w);
                uint64_t bp2 = pack2(bb.x, bb.y);
                uint64_t bp3 = pack2(bb.z, bb.w);
                #pragma unroll
                for (int p = 0; p < 4; p++) {
                    acc[0][p] = bp0; acc[1][p] = bp1; acc[2][p] = bp2; acc[3][p] = bp3;
                }
            }

            #pragma unroll 8
            for (int w = 0; w < WID; w++) {
                ulonglong2 wa = *(const ulonglong2*)&Wsm[w*WID + v0];      // pairs (v0,v0+1),(v0+2,v0+3)
                ulonglong2 wb = *(const ulonglong2*)&Wsm[w*WID + v0 + 4];  // pairs (v0+4,..),(v0+6,..)
                float4 hv = *(const float4*)&hin[w*NP + p0];
                uint64_t h0 = dup2(hv.x), h1 = dup2(hv.y), h2 = dup2(hv.z), h3 = dup2(hv.w);
                acc[0][0]=fma2(wa.x,h0,acc[0][0]); acc[0][1]=fma2(wa.x,h1,acc[0][1]);
                acc[0][2]=fma2(wa.x,h2,acc[0][2]); acc[0][3]=fma2(wa.x,h3,acc[0][3]);
                acc[1][0]=fma2(wa.y,h0,acc[1][0]); acc[1][1]=fma2(wa.y,h1,acc[1][1]);
                acc[1][2]=fma2(wa.y,h2,acc[1][2]); acc[1][3]=fma2(wa.y,h3,acc[1][3]);
                acc[2][0]=fma2(wb.x,h0,acc[2][0]); acc[2][1]=fma2(wb.x,h1,acc[2][1]);
                acc[2][2]=fma2(wb.x,h2,acc[2][2]); acc[2][3]=fma2(wb.x,h3,acc[2][3]);
                acc[3][0]=fma2(wb.y,h0,acc[3][0]); acc[3][1]=fma2(wb.y,h1,acc[3][1]);
                acc[3][2]=fma2(wb.y,h2,acc[3][2]); acc[3][3]=fma2(wb.y,h3,acc[3][3]);
            }

            // tanh + store (vectorized per neuron row).
            #pragma unroll
            for (int d = 0; d < 4; d++) {
                float a0,b0_,a1,b1_,a2,b2_,a3,b3_;
                unpack2(acc[d][0], a0, b0_);
                unpack2(acc[d][1], a1, b1_);
                unpack2(acc[d][2], a2, b2_);
                unpack2(acc[d][3], a3, b3_);
                float4 ra, rb;
                ra.x = fast_tanh(a0); ra.y = fast_tanh(a1); ra.z = fast_tanh(a2); ra.w = fast_tanh(a3);
                rb.x = fast_tanh(b0_); rb.y = fast_tanh(b1_); rb.z = fast_tanh(b2_); rb.w = fast_tanh(b3_);
                *(float4*)&hout[(v0 + 2*d    )*NP + p0] = ra;
                *(float4*)&hout[(v0 + 2*d + 1)*NP + p0] = rb;
            }
            __syncthreads();

            float* tmp = hin; hin = hout; hout = tmp;
        }

        // ---------- output layer + window ----------
        if (tid < NP) {
            const int p = tid;
            float raw = bout[s];
            const float* wo = Wout + s*WID;
            #pragma unroll 8
            for (int v = 0; v < WID; v++) raw = fmaf(wo[v], hin[v*NP + p], raw);

            const float x0v = xs[p];
            const float wlo = fast_sigmoid((x0v - mu_min[s]) / sd_min[s]);
            const float whi = fast_sigmoid((mu_max[s] - x0v) / sd_max[s]);
            result = fmaf(wlo * whi, raw, result);
        }
        // No explicit sync needed: next iteration's post-layer0 sync orders hB reuse.
        __syncthreads();
    }

    if (tid < NP) out[pblk + tid] = result;
}

extern "C" void kernel_launch(void* const* d_in, const int* in_sizes, int n_in,
                              void* d_out, int out_size) {
    const float* x       = (const float*)d_in[0];
    const float* W0      = (const float*)d_in[1];
    const float* b0      = (const float*)d_in[2];
    const float* Wh      = (const float*)d_in[3];
    const float* bh      = (const float*)d_in[4];
    const float* Wout    = (const float*)d_in[5];
    const float* bout    = (const float*)d_in[6];
    const float* centres = (const float*)d_in[7];
    const float* scales  = (const float*)d_in[8];
    const float* mu_min  = (const float*)d_in[9];
    const float* sd_min  = (const float*)d_in[10];
    const float* mu_max  = (const float*)d_in[11];
    const float* sd_max  = (const float*)d_in[12];
    float* out = (float*)d_out;

    const int smem_bytes = SMEM_FLOATS * (int)sizeof(float);
    static bool attr_set = false;
    if (!attr_set) {
        cudaFuncSetAttribute(fbpinn_f32x2_kernel,
                             cudaFuncAttributeMaxDynamicSharedMemorySize, smem_bytes);
        attr_set = true;
    }

    // 1) transpose hidden weights into g_WhT ([s][l][w][v])
    const int total = NSUB*NHID*WID*WID;
    transpose_wh_kernel<<<total/256, 256>>>(Wh);

    // 2) main kernel
    fbpinn_f32x2_kernel<<<NPTS/NP, THREADS, smem_bytes>>>(
        x, W0, b0, bh, Wout, bout, centres, scales,
        mu_min, sd_min, mu_max, sd_max, out);
}

// round 4
// speedup vs baseline: 3.0290x; 2.3844x over previous
#include <cuda_runtime.h>
#include <cuda_fp16.h>
#include <stdint.h>
#include <math.h>

// FBPINN via legacy tensor-core mma.sync (m16n8k16 f16, f32 acc), sm_103-safe PTX.
// 16 subs x (1->128->128->128->128->1, tanh), 65536 points.
// - fp32 accuracy via fp16 hi/lo split, 3-term MMA.
// - Activations chain in registers: C fragment == next layer's A fragment.
// - Weights pre-packed in fragment order -> one LDS.128 per B fragment,
//   cp.async double-buffered smem (2 x 64KB).

#define NSUB 16
#define WID  128
#define NHID 3
#define NSL  (NSUB*NHID)       // 48
#define NPTS 65536
#define NP   128               // points per CTA
#define THREADS 256            // 8 warps x 16 points
#define NCTAS (NPTS/NP)        // 512

#define W_SLOT_BYTES 65536
#define SM_XS (2*W_SLOT_BYTES)
#define SMEM_TOTAL (SM_XS + NP*4)

// Fragment-packed weights: [sl][j(16)][k(8)][lane(32)] x uint4{Bhi0,Bhi1,Blo0,Blo1}
__device__ uint4 g_Wpk[NSL*4096];

// ---------------- helpers ----------------
__device__ __forceinline__ uint32_t smem_u32(const void* p) {
    uint32_t a;
    asm("{ .reg .u64 t; cvta.to.shared.u64 t, %1; cvt.u32.u64 %0, t; }" : "=r"(a) : "l"(p));
    return a;
}
__device__ __forceinline__ float fast_tanh(float x) {
    float e = __expf(2.0f * x);
    return 1.0f - __fdividef(2.0f, e + 1.0f);
}
__device__ __forceinline__ float fast_sigmoid(float z) {
    return __fdividef(1.0f, 1.0f + __expf(-z));
}
__device__ __forceinline__ void pack_hilo(float f0, float f1, uint32_t& hi, uint32_t& lo) {
    __half2 h = __floats2half2_rn(f0, f1);
    float e0 = f0 - __low2float(h);
    float e1 = f1 - __high2float(h);
    __half2 l = __floats2half2_rn(e0, e1);
    hi = *reinterpret_cast<uint32_t*>(&h);
    lo = *reinterpret_cast<uint32_t*>(&l);
}

#define MMA16816(c, a, b0, b1) \
    asm volatile("mma.sync.aligned.m16n8k16.row.col.f32.f16.f16.f32 " \
        "{%0,%1,%2,%3}, {%4,%5,%6,%7}, {%8,%9}, {%0,%1,%2,%3};" \
        : "+f"((c)[0]), "+f"((c)[1]), "+f"((c)[2]), "+f"((c)[3]) \
        : "r"((a)[0]), "r"((a)[1]), "r"((a)[2]), "r"((a)[3]), "r"(b0), "r"(b1))

#define CP_ASYNC16(dst, src) \
    asm volatile("cp.async.cg.shared.global [%0], [%1], 16;" :: "r"(dst), "l"(src) : "memory")
#define CP_COMMIT() asm volatile("cp.async.commit_group;" ::: "memory")
#define CP_WAIT1()  asm volatile("cp.async.wait_group 1;" ::: "memory")

// ---------------- prep: pack weights into fragment order, fp16 hi/lo ----------------
__global__ void prep_pack(const float* __restrict__ Wh) {
    int idx = blockIdx.x * blockDim.x + threadIdx.x;   // < NSL*16*8*32
    int lane = idx & 31;
    int k    = (idx >> 5) & 7;
    int j    = (idx >> 8) & 15;
    int sl   = idx >> 12;
    int g = lane >> 2, t = lane & 3;
    int v = 8 * j + g;              // neuron (n of the mma)
    int w = 16 * k + 2 * t;         // input index (k of the mma)
    const float* row = Wh + ((size_t)sl * WID + v) * WID;
    float w0 = row[w], w1 = row[w + 1], w8 = row[w + 8], w9 = row[w + 9];

    __half2 h01 = __floats2half2_rn(w0, w1);
    __half2 h89 = __floats2half2_rn(w8, w9);
    float l0 = w0 - __low2float(h01), l1 = w1 - __high2float(h01);
    float l8 = w8 - __low2float(h89), l9 = w9 - __high2float(h89);
    __half2 lo01 = __floats2half2_rn(l0, l1);
    __half2 lo89 = __floats2half2_rn(l8, l9);

    uint4 o;
    o.x = *reinterpret_cast<uint32_t*>(&h01);
    o.y = *reinterpret_cast<uint32_t*>(&h89);
    o.z = *reinterpret_cast<uint32_t*>(&lo01);
    o.w = *reinterpret_cast<uint32_t*>(&lo89);
    g_Wpk[idx] = o;
}

// ---------------- stage one layer's packed weights via cp.async ----------------
__device__ __forceinline__ void stage_W(int sl, uint32_t dst_base, int tid) {
    const uint4* src = g_Wpk + (size_t)sl * 4096 + tid;
    uint32_t dst = dst_base + (uint32_t)tid * 16;
    #pragma unroll
    for (int i = 0; i < 16; i++) {
        CP_ASYNC16(dst + (uint32_t)i * 4096u, src + i * 256);
    }
}

// ---------------- main kernel ----------------
__global__ void __launch_bounds__(THREADS, 1) fbpinn_mma_kernel(
    const float* __restrict__ x,
    const float* __restrict__ W0,      // [16,128]
    const float* __restrict__ b0,      // [16,128]
    const float* __restrict__ bh,      // [16,3,128]
    const float* __restrict__ Wout,    // [16,128]
    const float* __restrict__ bout,    // [16]
    const float* __restrict__ centres,
    const float* __restrict__ scales,
    const float* __restrict__ mu_min,
    const float* __restrict__ sd_min,
    const float* __restrict__ mu_max,
    const float* __restrict__ sd_max,
    float* __restrict__ out)
{
    extern __shared__ char smem[];
    const uint32_t sb = smem_u32(smem);
    float* xs = (float*)(smem + SM_XS);

    const int tid  = threadIdx.x;
    const int lane = tid & 31;
    const int w    = tid >> 5;        // warp 0..7
    const int g    = lane >> 2;       // 0..7
    const int t    = lane & 3;        // 0..3
    const int pblk = blockIdx.x * NP;
    const int r0 = w * 16 + g;        // point row (local)
    const int r1 = r0 + 8;

    if (tid < NP) xs[tid] = x[pblk + tid];

    // Prologue: stage sl=0 and sl=1
    stage_W(0, sb, tid);                 CP_COMMIT();
    stage_W(1, sb + W_SLOT_BYTES, tid);  CP_COMMIT();
    __syncthreads();   // xs visible

    const float x0v = xs[r0];
    const float x1v = xs[r1];

    float res0 = 0.0f, res1 = 0.0f;

    uint32_t Ahi[8][4], Alo[8][4];

    for (int s = 0; s < NSUB; s++) {
        const float centre = __ldg(&centres[s]);
        const float inv_scale = 1.0f / fmaxf(__ldg(&scales[s]), 1e-8f);
        const float xi0 = (x0v - centre) * inv_scale;
        const float xi1 = (x1v - centre) * inv_scale;

        // ---- layer 0: build A fragments directly ----
        const float* W0p = W0 + s * WID;
        const float* b0p = b0 + s * WID;
        #pragma unroll
        for (int kf = 0; kf < 8; kf++) {
            const int vb = 16 * kf + 2 * t;
            const float wv0 = __ldg(&W0p[vb]),     bv0 = __ldg(&b0p[vb]);
            const float wv1 = __ldg(&W0p[vb + 1]), bv1 = __ldg(&b0p[vb + 1]);
            const float wv8 = __ldg(&W0p[vb + 8]), bv8 = __ldg(&b0p[vb + 8]);
            const float wv9 = __ldg(&W0p[vb + 9]), bv9 = __ldg(&b0p[vb + 9]);
            float h00 = fast_tanh(fmaf(wv0, xi0, bv0));
            float h01 = fast_tanh(fmaf(wv1, xi0, bv1));
            float h10 = fast_tanh(fmaf(wv0, xi1, bv0));
            float h11 = fast_tanh(fmaf(wv1, xi1, bv1));
            float h08 = fast_tanh(fmaf(wv8, xi0, bv8));
            float h09 = fast_tanh(fmaf(wv9, xi0, bv9));
            float h18 = fast_tanh(fmaf(wv8, xi1, bv8));
            float h19 = fast_tanh(fmaf(wv9, xi1, bv9));
            pack_hilo(h00, h01, Ahi[kf][0], Alo[kf][0]);
            pack_hilo(h10, h11, Ahi[kf][1], Alo[kf][1]);
            pack_hilo(h08, h09, Ahi[kf][2], Alo[kf][2]);
            pack_hilo(h18, h19, Ahi[kf][3], Alo[kf][3]);
        }

        // ---- hidden layers ----
        for (int l = 0; l < NHID; l++) {
            const int sl = s * NHID + l;
            const uint32_t slot = sb + (uint32_t)(sl & 1) * W_SLOT_BYTES;

            CP_WAIT1();
            __syncthreads();

            // init acc with bias
            float acc[16][4];
            const float* bhp = bh + sl * WID;
            #pragma unroll
            for (int j = 0; j < 16; j++) {
                const float bv0 = __ldg(&bhp[8 * j + 2 * t]);
                const float bv1 = __ldg(&bhp[8 * j + 2 * t + 1]);
                acc[j][0] = bv0; acc[j][1] = bv1; acc[j][2] = bv0; acc[j][3] = bv1;
            }

            // GEMM: 16 n-tiles x 8 k-steps x 3 terms
            #pragma unroll
            for (int k = 0; k < 8; k++) {
                #pragma unroll
                for (int j = 0; j < 16; j++) {
                    const uint4 bf = *reinterpret_cast<const uint4*>(
                        (const char*)smem + (slot - sb) + (((j * 8 + k) * 32 + lane) << 4));
                    MMA16816(acc[j], Ahi[k], bf.x, bf.y);
                    MMA16816(acc[j], Ahi[k], bf.z, bf.w);
                    MMA16816(acc[j], Alo[k], bf.x, bf.y);
                }
            }

            __syncthreads();   // all warps done reading this slot
            if (sl + 2 < NSL) stage_W(sl + 2, slot, tid);
            CP_COMMIT();

            if (l < NHID - 1) {
                // epilogue: tanh -> fp16 hi/lo -> next A fragments
                #pragma unroll
                for (int kf = 0; kf < 8; kf++) {
                    const int j0 = 2 * kf, j1 = 2 * kf + 1;
                    pack_hilo(fast_tanh(acc[j0][0]), fast_tanh(acc[j0][1]), Ahi[kf][0], Alo[kf][0]);
                    pack_hilo(fast_tanh(acc[j0][2]), fast_tanh(acc[j0][3]), Ahi[kf][1], Alo[kf][1]);
                    pack_hilo(fast_tanh(acc[j1][0]), fast_tanh(acc[j1][1]), Ahi[kf][2], Alo[kf][2]);
                    pack_hilo(fast_tanh(acc[j1][2]), fast_tanh(acc[j1][3]), Ahi[kf][3], Alo[kf][3]);
                }
            } else {
                // final: fold output layer + window
                float p0 = 0.0f, p1 = 0.0f;
                const float* wop = Wout + s * WID;
                #pragma unroll
                for (int j = 0; j < 16; j++) {
                    const float wv0 = __ldg(&wop[8 * j + 2 * t]);
                    const float wv1 = __ldg(&wop[8 * j + 2 * t + 1]);
                    p0 = fmaf(wv0, fast_tanh(acc[j][0]), p0);
                    p0 = fmaf(wv1, fast_tanh(acc[j][1]), p0);
                    p1 = fmaf(wv0, fast_tanh(acc[j][2]), p1);
                    p1 = fmaf(wv1, fast_tanh(acc[j][3]), p1);
                }
                p0 += __shfl_xor_sync(0xFFFFFFFF, p0, 1);
                p0 += __shfl_xor_sync(0xFFFFFFFF, p0, 2);
                p1 += __shfl_xor_sync(0xFFFFFFFF, p1, 1);
                p1 += __shfl_xor_sync(0xFFFFFFFF, p1, 2);

                const float bo = __ldg(&bout[s]);
                const float mmin = __ldg(&mu_min[s]), smin = __ldg(&sd_min[s]);
                const float mmax = __ldg(&mu_max[s]), smax = __ldg(&sd_max[s]);
                const float wm0 = fast_sigmoid((x0v - mmin) / smin) *
                                  fast_sigmoid((mmax - x0v) / smax);
                const float wm1 = fast_sigmoid((x1v - mmin) / smin) *
                                  fast_sigmoid((mmax - x1v) / smax);
                res0 = fmaf(wm0, p0 + bo, res0);
                res1 = fmaf(wm1, p1 + bo, res1);
            }
        }
    }

    if (t == 0) {
        out[pblk + r0] = res0;
        out[pblk + r1] = res1;
    }
}

// ---------------- launch ----------------
extern "C" void kernel_launch(void* const* d_in, const int* in_sizes, int n_in,
                              void* d_out, int out_size) {
    const float* x       = (const float*)d_in[0];
    const float* W0      = (const float*)d_in[1];
    const float* b0      = (const float*)d_in[2];
    const float* Wh      = (const float*)d_in[3];
    const float* bh      = (const float*)d_in[4];
    const float* Wout    = (const float*)d_in[5];
    const float* bout    = (const float*)d_in[6];
    const float* centres = (const float*)d_in[7];
    const float* scales  = (const float*)d_in[8];
    const float* mu_min  = (const float*)d_in[9];
    const float* sd_min  = (const float*)d_in[10];
    const float* mu_max  = (const float*)d_in[11];
    const float* sd_max  = (const float*)d_in[12];
    float* out = (float*)d_out;

    cudaFuncSetAttribute(fbpinn_mma_kernel,
                         cudaFuncAttributeMaxDynamicSharedMemorySize, SMEM_TOTAL);

    prep_pack<<<(NSL * 4096) / 256, 256>>>(Wh);

    fbpinn_mma_kernel<<<NCTAS, THREADS, SMEM_TOTAL>>>(
        x, W0, b0, bh, Wout, bout, centres, scales,
        mu_min, sd_min, mu_max, sd_max, out);
}

// round 5
// speedup vs baseline: 3.6179x; 1.1944x over previous
#include <cuda_runtime.h>
#include <cuda_fp16.h>
#include <stdint.h>
#include <math.h>

// FBPINN via mma.sync m16n8k16 (fp16 in, fp32 acc), sm_103-safe PTX.
// R5: 2-term precision split (A_hi*B_hi + A_hi*B_lo); B-fragment reg prefetch.
// Activations chain in registers (C frag == next A frag). cp.async double buffer.

#define NSUB 16
#define WID  128
#define NHID 3
#define NSL  (NSUB*NHID)       // 48
#define NPTS 65536
#define NP   128               // points per CTA
#define THREADS 256            // 8 warps x 16 points
#define NCTAS (NPTS/NP)        // 512

#define W_SLOT_BYTES 65536
#define SM_XS (2*W_SLOT_BYTES)
#define SMEM_TOTAL (SM_XS + NP*4)

// Fragment-packed weights: [sl][j(16)][k(8)][lane(32)] x uint4{Bhi0,Bhi1,Blo0,Blo1}
__device__ uint4 g_Wpk[NSL*4096];

// ---------------- helpers ----------------
__device__ __forceinline__ uint32_t smem_u32(const void* p) {
    uint32_t a;
    asm("{ .reg .u64 t; cvta.to.shared.u64 t, %1; cvt.u32.u64 %0, t; }" : "=r"(a) : "l"(p));
    return a;
}
__device__ __forceinline__ float fast_tanh(float x) {
    float e = __expf(2.0f * x);
    return 1.0f - __fdividef(2.0f, e + 1.0f);
}
__device__ __forceinline__ float fast_sigmoid(float z) {
    return __fdividef(1.0f, 1.0f + __expf(-z));
}
__device__ __forceinline__ uint32_t pack_hi(float f0, float f1) {
    __half2 h = __floats2half2_rn(f0, f1);
    return *reinterpret_cast<uint32_t*>(&h);
}

#define MMA16816(c, a, b0, b1) \
    asm volatile("mma.sync.aligned.m16n8k16.row.col.f32.f16.f16.f32 " \
        "{%0,%1,%2,%3}, {%4,%5,%6,%7}, {%8,%9}, {%0,%1,%2,%3};" \
        : "+f"((c)[0]), "+f"((c)[1]), "+f"((c)[2]), "+f"((c)[3]) \
        : "r"((a)[0]), "r"((a)[1]), "r"((a)[2]), "r"((a)[3]), "r"(b0), "r"(b1))

#define CP_ASYNC16(dst, src) \
    asm volatile("cp.async.cg.shared.global [%0], [%1], 16;" :: "r"(dst), "l"(src) : "memory")
#define CP_COMMIT() asm volatile("cp.async.commit_group;" ::: "memory")
#define CP_WAIT1()  asm volatile("cp.async.wait_group 1;" ::: "memory")

// ---------------- prep: pack weights into fragment order, fp16 hi/lo ----------------
__global__ void prep_pack(const float* __restrict__ Wh) {
    int idx = blockIdx.x * blockDim.x + threadIdx.x;   // < NSL*16*8*32
    int lane = idx & 31;
    int k    = (idx >> 5) & 7;
    int j    = (idx >> 8) & 15;
    int sl   = idx >> 12;
    int g = lane >> 2, t = lane & 3;
    int v = 8 * j + g;              // neuron (n of the mma)
    int w = 16 * k + 2 * t;         // input index (k of the mma)
    const float* row = Wh + ((size_t)sl * WID + v) * WID;
    float w0 = row[w], w1 = row[w + 1], w8 = row[w + 8], w9 = row[w + 9];

    __half2 h01 = __floats2half2_rn(w0, w1);
    __half2 h89 = __floats2half2_rn(w8, w9);
    float l0 = w0 - __low2float(h01), l1 = w1 - __high2float(h01);
    float l8 = w8 - __low2float(h89), l9 = w9 - __high2float(h89);
    __half2 lo01 = __floats2half2_rn(l0, l1);
    __half2 lo89 = __floats2half2_rn(l8, l9);

    uint4 o;
    o.x = *reinterpret_cast<uint32_t*>(&h01);
    o.y = *reinterpret_cast<uint32_t*>(&h89);
    o.z = *reinterpret_cast<uint32_t*>(&lo01);
    o.w = *reinterpret_cast<uint32_t*>(&lo89);
    g_Wpk[idx] = o;
}

// ---------------- stage one layer's packed weights via cp.async ----------------
__device__ __forceinline__ void stage_W(int sl, uint32_t dst_base, int tid) {
    const uint4* src = g_Wpk + (size_t)sl * 4096 + tid;
    uint32_t dst = dst_base + (uint32_t)tid * 16;
    #pragma unroll
    for (int i = 0; i < 16; i++) {
        CP_ASYNC16(dst + (uint32_t)i * 4096u, src + i * 256);
    }
}

// ---------------- main kernel ----------------
__global__ void __launch_bounds__(THREADS, 1) fbpinn_mma_kernel(
    const float* __restrict__ x,
    const float* __restrict__ W0,      // [16,128]
    const float* __restrict__ b0,      // [16,128]
    const float* __restrict__ bh,      // [16,3,128]
    const float* __restrict__ Wout,    // [16,128]
    const float* __restrict__ bout,    // [16]
    const float* __restrict__ centres,
    const float* __restrict__ scales,
    const float* __restrict__ mu_min,
    const float* __restrict__ sd_min,
    const float* __restrict__ mu_max,
    const float* __restrict__ sd_max,
    float* __restrict__ out)
{
    extern __shared__ char smem[];
    const uint32_t sb = smem_u32(smem);
    float* xs = (float*)(smem + SM_XS);

    const int tid  = threadIdx.x;
    const int lane = tid & 31;
    const int w    = tid >> 5;        // warp 0..7
    const int g    = lane >> 2;       // 0..7
    const int t    = lane & 3;        // 0..3
    const int pblk = blockIdx.x * NP;
    const int r0 = w * 16 + g;        // point row (local)
    const int r1 = r0 + 8;

    if (tid < NP) xs[tid] = x[pblk + tid];

    // Prologue: stage sl=0 and sl=1
    stage_W(0, sb, tid);                 CP_COMMIT();
    stage_W(1, sb + W_SLOT_BYTES, tid);  CP_COMMIT();
    __syncthreads();   // xs visible

    const float x0v = xs[r0];
    const float x1v = xs[r1];

    float res0 = 0.0f, res1 = 0.0f;

    uint32_t Ahi[8][4];

    for (int s = 0; s < NSUB; s++) {
        const float centre = __ldg(&centres[s]);
        const float inv_scale = 1.0f / fmaxf(__ldg(&scales[s]), 1e-8f);
        const float xi0 = (x0v - centre) * inv_scale;
        const float xi1 = (x1v - centre) * inv_scale;

        // ---- layer 0: build A fragments directly ----
        const float* W0p = W0 + s * WID;
        const float* b0p = b0 + s * WID;
        #pragma unroll
        for (int kf = 0; kf < 8; kf++) {
            const int vb = 16 * kf + 2 * t;
            const float wv0 = __ldg(&W0p[vb]),     bv0 = __ldg(&b0p[vb]);
            const float wv1 = __ldg(&W0p[vb + 1]), bv1 = __ldg(&b0p[vb + 1]);
            const float wv8 = __ldg(&W0p[vb + 8]), bv8 = __ldg(&b0p[vb + 8]);
            const float wv9 = __ldg(&W0p[vb + 9]), bv9 = __ldg(&b0p[vb + 9]);
            Ahi[kf][0] = pack_hi(fast_tanh(fmaf(wv0, xi0, bv0)), fast_tanh(fmaf(wv1, xi0, bv1)));
            Ahi[kf][1] = pack_hi(fast_tanh(fmaf(wv0, xi1, bv0)), fast_tanh(fmaf(wv1, xi1, bv1)));
            Ahi[kf][2] = pack_hi(fast_tanh(fmaf(wv8, xi0, bv8)), fast_tanh(fmaf(wv9, xi0, bv9)));
            Ahi[kf][3] = pack_hi(fast_tanh(fmaf(wv8, xi1, bv8)), fast_tanh(fmaf(wv9, xi1, bv9)));
        }

        // ---- hidden layers ----
        for (int l = 0; l < NHID; l++) {
            const int sl = s * NHID + l;
            const uint32_t slot = sb + (uint32_t)(sl & 1) * W_SLOT_BYTES;

            CP_WAIT1();
            __syncthreads();

            // init acc with bias
            float acc[16][4];
            const float* bhp = bh + sl * WID;
            #pragma unroll
            for (int j = 0; j < 16; j++) {
                const float bv0 = __ldg(&bhp[8 * j + 2 * t]);
                const float bv1 = __ldg(&bhp[8 * j + 2 * t + 1]);
                acc[j][0] = bv0; acc[j][1] = bv1; acc[j][2] = bv0; acc[j][3] = bv1;
            }

            // GEMM: 16 n-tiles x 8 k-steps x 2 terms, with B-fragment prefetch
            const uint32_t bbase = slot + ((uint32_t)lane << 4);
            uint4 bf = *reinterpret_cast<const uint4*>(
                (const char*)smem + (bbase - sb));
            #pragma unroll
            for (int k = 0; k < 8; k++) {
                #pragma unroll
                for (int j = 0; j < 16; j++) {
                    const uint4 cur = bf;
                    // prefetch next fragment (j+1, same k) or (0, k+1)
                    const int nj = (j == 15) ? 0 : (j + 1);
                    const int nk = (j == 15) ? (k == 7 ? 0 : k + 1) : k;
                    bf = *reinterpret_cast<const uint4*>(
                        (const char*)smem + (bbase - sb) + (uint32_t)((nj * 8 + nk) << 9));
                    MMA16816(acc[j], Ahi[k], cur.x, cur.y);
                    MMA16816(acc[j], Ahi[k], cur.z, cur.w);
                }
            }

            __syncthreads();   // all warps done reading this slot
            if (sl + 2 < NSL) stage_W(sl + 2, slot, tid);
            CP_COMMIT();

            if (l < NHID - 1) {
                // epilogue: tanh -> fp16 -> next A fragments
                #pragma unroll
                for (int kf = 0; kf < 8; kf++) {
                    const int j0 = 2 * kf, j1 = 2 * kf + 1;
                    Ahi[kf][0] = pack_hi(fast_tanh(acc[j0][0]), fast_tanh(acc[j0][1]));
                    Ahi[kf][1] = pack_hi(fast_tanh(acc[j0][2]), fast_tanh(acc[j0][3]));
                    Ahi[kf][2] = pack_hi(fast_tanh(acc[j1][0]), fast_tanh(acc[j1][1]));
                    Ahi[kf][3] = pack_hi(fast_tanh(acc[j1][2]), fast_tanh(acc[j1][3]));
                }
            } else {
                // final: fold output layer + window
                float p0 = 0.0f, p1 = 0.0f;
                const float* wop = Wout + s * WID;
                #pragma unroll
                for (int j = 0; j < 16; j++) {
                    const float wv0 = __ldg(&wop[8 * j + 2 * t]);
                    const float wv1 = __ldg(&wop[8 * j + 2 * t + 1]);
                    p0 = fmaf(wv0, fast_tanh(acc[j][0]), p0);
                    p0 = fmaf(wv1, fast_tanh(acc[j][1]), p0);
                    p1 = fmaf(wv0, fast_tanh(acc[j][2]), p1);
                    p1 = fmaf(wv1, fast_tanh(acc[j][3]), p1);
                }
                p0 += __shfl_xor_sync(0xFFFFFFFF, p0, 1);
                p0 += __shfl_xor_sync(0xFFFFFFFF, p0, 2);
                p1 += __shfl_xor_sync(0xFFFFFFFF, p1, 1);
                p1 += __shfl_xor_sync(0xFFFFFFFF, p1, 2);

                const float bo = __ldg(&bout[s]);
                const float mmin = __ldg(&mu_min[s]), smin = __ldg(&sd_min[s]);
                const float mmax = __ldg(&mu_max[s]), smax = __ldg(&sd_max[s]);
                const float wm0 = fast_sigmoid((x0v - mmin) / smin) *
                                  fast_sigmoid((mmax - x0v) / smax);
                const float wm1 = fast_sigmoid((x1v - mmin) / smin) *
                                  fast_sigmoid((mmax - x1v) / smax);
                res0 = fmaf(wm0, p0 + bo, res0);
                res1 = fmaf(wm1, p1 + bo, res1);
            }
        }
    }

    if (t == 0) {
        out[pblk + r0] = res0;
        out[pblk + r1] = res1;
    }
}

// ---------------- launch ----------------
extern "C" void kernel_launch(void* const* d_in, const int* in_sizes, int n_in,
                              void* d_out, int out_size) {
    const float* x       = (const float*)d_in[0];
    const float* W0      = (const float*)d_in[1];
    const float* b0      = (const float*)d_in[2];
    const float* Wh      = (const float*)d_in[3];
    const float* bh      = (const float*)d_in[4];
    const float* Wout    = (const float*)d_in[5];
    const float* bout    = (const float*)d_in[6];
    const float* centres = (const float*)d_in[7];
    const float* scales  = (const float*)d_in[8];
    const float* mu_min  = (const float*)d_in[9];
    const float* sd_min  = (const float*)d_in[10];
    const float* mu_max  = (const float*)d_in[11];
    const float* sd_max  = (const float*)d_in[12];
    float* out = (float*)d_out;

    cudaFuncSetAttribute(fbpinn_mma_kernel,
                         cudaFuncAttributeMaxDynamicSharedMemorySize, SMEM_TOTAL);

    prep_pack<<<(NSL * 4096) / 256, 256>>>(Wh);

    fbpinn_mma_kernel<<<NCTAS, THREADS, SMEM_TOTAL>>>(
        x, W0, b0, bh, Wout, bout, centres, scales,
        mu_min, sd_min, mu_max, sd_max, out);
}